// round 1
// baseline (speedup 1.0000x reference)
#include <cuda_runtime.h>
#include <math.h>

#define DD 64
#define NMAX 100000
#define EMAX 1200000

// Scratch (no cudaMalloc allowed)
__device__ float g_z[NMAX * DD];   // transformed features z = xW^T + b
__device__ float g_e[EMAX];        // per-edge scores, then exp values
__device__ float g_m[NMAX];        // per-node max score
__device__ float g_s[NMAX];        // per-node softmax denominator

// float atomic max via int/uint monotonic bit tricks
__device__ __forceinline__ void atomicMaxFloat(float* addr, float value) {
    if (value >= 0.0f)
        atomicMax((int*)addr, __float_as_int(value));
    else
        atomicMin((unsigned int*)addr, __float_as_uint(value));
}

// K1: z = x @ W^T + b   (z[n][d] = sum_k x[n][k] * W[d][k] + b[d])
// 256 threads = 4 rows x 64 dims per block. W transposed into padded smem.
__global__ void k_gemm(const float* __restrict__ x, const float* __restrict__ W,
                       const float* __restrict__ b, int N) {
    __shared__ float Wt[DD][DD + 1];  // Wt[k][d] = W[d][k], padded vs bank conflicts
    __shared__ float xs[4][DD];
    int tid = threadIdx.x;
    for (int i = tid; i < DD * DD; i += 256) {
        int d = i >> 6, k = i & 63;
        Wt[k][d] = W[i];
    }
    int r = tid >> 6;
    int d = tid & 63;
    int row = blockIdx.x * 4 + r;
    if (row < N) xs[r][d] = x[row * DD + d];
    __syncthreads();
    if (row >= N) return;
    float acc = b[d];
#pragma unroll
    for (int k = 0; k < DD; k++)
        acc = fmaf(xs[r][k], Wt[k][d], acc);
    g_z[row * DD + d] = acc;
}

// K2: init m = -inf, s = 0, out = 0
__global__ void k_init(float* __restrict__ out, int N) {
    int i = blockIdx.x * blockDim.x + threadIdx.x;
    int total = N * DD;
    if (i < total) out[i] = 0.0f;
    if (i < N) {
        g_m[i] = -INFINITY;
        g_s[i] = 0.0f;
    }
}

// K3: per-edge score e = att . leakyrelu(z[src] + z[dst]); segment max into g_m.
// One warp per edge; lane handles 2 dims (float2).
__global__ void k_score(const int* __restrict__ src, const int* __restrict__ dst,
                        const float* __restrict__ att, int E) {
    int warp = (blockIdx.x * blockDim.x + threadIdx.x) >> 5;
    int lane = threadIdx.x & 31;
    if (warp >= E) return;
    int sj = src[warp];
    int di = dst[warp];
    float2 zs = *(const float2*)(g_z + (size_t)sj * DD + lane * 2);
    float2 zd = *(const float2*)(g_z + (size_t)di * DD + lane * 2);
    float2 a  = *(const float2*)(att + lane * 2);
    float u = zs.x + zd.x; u = (u > 0.0f) ? u : 0.2f * u;
    float v = zs.y + zd.y; v = (v > 0.0f) ? v : 0.2f * v;
    float p = u * a.x + v * a.y;
#pragma unroll
    for (int o = 16; o; o >>= 1) p += __shfl_xor_sync(0xFFFFFFFFu, p, o);
    if (lane == 0) {
        g_e[warp] = p;
        atomicMaxFloat(&g_m[di], p);
    }
}

// K4: per-edge ex = exp(e - m[dst]); accumulate s[dst] and UNNORMALIZED
//     out[dst] += ex * x[src]  (normalization deferred to K5).
__global__ void k_accum(const float* __restrict__ x, const int* __restrict__ src,
                        const int* __restrict__ dst, float* __restrict__ out, int E) {
    int warp = (blockIdx.x * blockDim.x + threadIdx.x) >> 5;
    int lane = threadIdx.x & 31;
    if (warp >= E) return;
    int sj = src[warp];
    int di = dst[warp];
    float ex = expf(g_e[warp] - g_m[di]);
    if (lane == 0) atomicAdd(&g_s[di], ex);
    float2 xv = *(const float2*)(x + (size_t)sj * DD + lane * 2);
    float* o = out + (size_t)di * DD + lane * 2;
    atomicAdd(o,     ex * xv.x);
    atomicAdd(o + 1, ex * xv.y);
}

// K5: out[n][:] /= s[n]  (empty segments stay 0)
__global__ void k_norm(float* __restrict__ out, int N) {
    int i = blockIdx.x * blockDim.x + threadIdx.x;
    if (i >= N * DD) return;
    float s = g_s[i >> 6];
    if (s > 0.0f) out[i] /= s;
}

extern "C" void kernel_launch(void* const* d_in, const int* in_sizes, int n_in,
                              void* d_out, int out_size) {
    const float* x   = (const float*)d_in[0];
    const int*   ei  = (const int*)d_in[1];
    const float* W   = (const float*)d_in[2];
    const float* b   = (const float*)d_in[3];
    const float* att = (const float*)d_in[4];
    float* out = (float*)d_out;

    int N = in_sizes[0] / DD;
    int E = in_sizes[1] / 2;
    const int* src = ei;
    const int* dst = ei + E;

    k_gemm<<<(N + 3) / 4, 256>>>(x, W, b, N);
    k_init<<<(N * DD + 255) / 256, 256>>>(out, N);

    int edge_blocks = (int)(((long long)E * 32 + 255) / 256);
    k_score<<<edge_blocks, 256>>>(src, dst, att, E);
    k_accum<<<edge_blocks, 256>>>(x, src, dst, out, E);

    k_norm<<<(N * DD + 255) / 256, 256>>>(out, N);
}

// round 2
// speedup vs baseline: 1.7878x; 1.7878x over previous
#include <cuda_runtime.h>
#include <math.h>

#define DD 64
#define NMAX 100000
#define EMAX 1200000
#define SCAN_B 1024
#define NBLK ((NMAX + SCAN_B - 1) / SCAN_B)   // 98

// Scratch (static __device__; no cudaMalloc allowed)
__device__ float g_zx[NMAX * 2 * DD];  // per node: interleaved {z[2l],z[2l+1],x[2l],x[2l+1]} x 32
__device__ int   g_deg[NMAX];
__device__ int   g_rowstart[NMAX];     // exclusive prefix sum of deg
__device__ int   g_cursor[NMAX];
__device__ int   g_csrc[EMAX];         // src ids sorted by dst
__device__ int   g_bsum[NBLK];
__device__ int   g_bofs[NBLK];

// ---------------- K1: GEMM  z = x @ W^T + b, write interleaved zx ----------------
__global__ void k_gemm(const float* __restrict__ x, const float* __restrict__ W,
                       const float* __restrict__ b, int N) {
    __shared__ float Wt[DD][DD + 1];
    __shared__ float xs[4][DD];
    __shared__ float zs[4][DD];
    int tid = threadIdx.x;
    for (int i = tid; i < DD * DD; i += 256) {
        int d = i >> 6, k = i & 63;
        Wt[k][d] = W[i];
    }
    int r = tid >> 6;
    int d = tid & 63;
    int row = blockIdx.x * 4 + r;
    if (row < N) xs[r][d] = x[row * DD + d];
    __syncthreads();
    if (row < N) {
        float acc = b[d];
#pragma unroll
        for (int k = 0; k < DD; k++)
            acc = fmaf(xs[r][k], Wt[k][d], acc);
        zs[r][d] = acc;
    }
    __syncthreads();
    if (row < N && d < 32) {
        float4 v = make_float4(zs[r][2 * d], zs[r][2 * d + 1],
                               xs[r][2 * d], xs[r][2 * d + 1]);
        ((float4*)g_zx)[(size_t)row * 32 + d] = v;
    }
}

// ---------------- CSR build ----------------
__global__ void k_zero_deg(int N) {
    int i = blockIdx.x * blockDim.x + threadIdx.x;
    if (i < N) g_deg[i] = 0;
}

__global__ void k_hist(const int* __restrict__ dst, int E) {
    int e = blockIdx.x * blockDim.x + threadIdx.x;
    if (e < E) atomicAdd(&g_deg[dst[e]], 1);
}

// scan1: per-block exclusive scan of deg -> g_rowstart (local), block sums -> g_bsum
__global__ void k_scan1(int N) {
    __shared__ int sm[SCAN_B];
    int t = threadIdx.x;
    int gi = blockIdx.x * SCAN_B + t;
    int v = (gi < N) ? g_deg[gi] : 0;
    sm[t] = v;
    __syncthreads();
#pragma unroll
    for (int o = 1; o < SCAN_B; o <<= 1) {
        int u = (t >= o) ? sm[t - o] : 0;
        __syncthreads();
        sm[t] += u;
        __syncthreads();
    }
    if (gi < N) g_rowstart[gi] = sm[t] - v;
    if (t == SCAN_B - 1) g_bsum[blockIdx.x] = sm[t];
}

// scan2: single block scans NBLK block sums -> exclusive g_bofs
__global__ void k_scan2() {
    __shared__ int sm[128];
    int t = threadIdx.x;
    int v = (t < NBLK) ? g_bsum[t] : 0;
    sm[t] = v;
    __syncthreads();
#pragma unroll
    for (int o = 1; o < 128; o <<= 1) {
        int u = (t >= o) ? sm[t - o] : 0;
        __syncthreads();
        sm[t] += u;
        __syncthreads();
    }
    if (t < NBLK) g_bofs[t] = sm[t] - v;
}

// scan3: add block offsets; zero cursors
__global__ void k_scan3(int N) {
    int i = blockIdx.x * blockDim.x + threadIdx.x;
    if (i < N) {
        g_rowstart[i] += g_bofs[i >> 10];
        g_cursor[i] = 0;
    }
}

__global__ void k_scatter(const int* __restrict__ src, const int* __restrict__ dst, int E) {
    int e = blockIdx.x * blockDim.x + threadIdx.x;
    if (e >= E) return;
    int d = dst[e];
    int pos = g_rowstart[d] + atomicAdd(&g_cursor[d], 1);
    g_csrc[pos] = src[e];
}

// ---------------- Main: warp per node; online softmax + weighted sum ----------------
__global__ void k_main(const float* __restrict__ att, float* __restrict__ out, int N) {
    int node = (blockIdx.x * blockDim.x + threadIdx.x) >> 5;
    int lane = threadIdx.x & 31;
    if (node >= N) return;

    const float4* ZX = (const float4*)g_zx;
    float4 me = ZX[(size_t)node * 32 + lane];   // me.x,me.y = z_i pair
    float2 a = ((const float2*)att)[lane];

    int start = g_rowstart[node];
    int deg = g_deg[node];

    float m = -INFINITY, s = 0.0f, acc0 = 0.0f, acc1 = 0.0f;

    for (int base = 0; base < deg; base += 32) {
        int nchunk = min(32, deg - base);
        int jv = (base + lane < deg) ? g_csrc[start + base + lane] : 0;
        for (int k = 0; k < nchunk; k++) {
            int j = __shfl_sync(0xFFFFFFFFu, jv, k);
            float4 v = ZX[(size_t)j * 32 + lane];   // z_j pair, x_j pair
            float u0 = v.x + me.x; u0 = (u0 > 0.0f) ? u0 : 0.2f * u0;
            float u1 = v.y + me.y; u1 = (u1 > 0.0f) ? u1 : 0.2f * u1;
            float p = u0 * a.x + u1 * a.y;
#pragma unroll
            for (int o = 16; o; o >>= 1) p += __shfl_xor_sync(0xFFFFFFFFu, p, o);
            float nm = fmaxf(m, p);
            float sc = __expf(m - nm);   // m=-inf first iter -> 0
            float w  = __expf(p - nm);
            s    = s    * sc + w;
            acc0 = acc0 * sc + w * v.z;
            acc1 = acc1 * sc + w * v.w;
            m = nm;
        }
    }

    float inv = (s > 0.0f) ? (1.0f / s) : 0.0f;
    ((float2*)out)[(size_t)node * 32 + lane] = make_float2(acc0 * inv, acc1 * inv);
}

extern "C" void kernel_launch(void* const* d_in, const int* in_sizes, int n_in,
                              void* d_out, int out_size) {
    const float* x   = (const float*)d_in[0];
    const int*   ei  = (const int*)d_in[1];
    const float* W   = (const float*)d_in[2];
    const float* b   = (const float*)d_in[3];
    const float* att = (const float*)d_in[4];
    float* out = (float*)d_out;

    int N = in_sizes[0] / DD;
    int E = in_sizes[1] / 2;
    const int* src = ei;
    const int* dst = ei + E;

    k_gemm<<<(N + 3) / 4, 256>>>(x, W, b, N);

    k_zero_deg<<<(N + 255) / 256, 256>>>(N);
    k_hist<<<(E + 255) / 256, 256>>>(dst, E);
    k_scan1<<<(N + SCAN_B - 1) / SCAN_B, SCAN_B>>>(N);
    k_scan2<<<1, 128>>>();
    k_scan3<<<(N + 255) / 256, 256>>>(N);
    k_scatter<<<(E + 255) / 256, 256>>>(src, dst, E);

    k_main<<<(N * 32 + 255) / 256, 256>>>(att, out, N);
}

// round 3
// speedup vs baseline: 1.9254x; 1.0770x over previous
#include <cuda_runtime.h>
#include <math.h>

#define DD 64
#define NMAX 100000
#define EMAX 1200000
#define SCAN_B 1024
#define NBLK ((NMAX + SCAN_B - 1) / SCAN_B)   // 98
#define GR 64   // gemm rows per block

// Scratch (static __device__; no cudaMalloc allowed)
__device__ float g_z[NMAX * DD];       // transformed features z = xW^T + b
__device__ int   g_deg[NMAX];
__device__ int   g_rowstart[NMAX];     // exclusive prefix sum of deg
__device__ int   g_cursor[NMAX];
__device__ int   g_csrc[EMAX];         // src ids sorted by dst
__device__ int   g_bsum[NBLK];
__device__ int   g_bofs[NBLK];

// ---------------- K1: GEMM  z = x @ W^T + b  (4x4 register tiling) ----------------
__global__ void k_gemm(const float* __restrict__ x, const float* __restrict__ W,
                       const float* __restrict__ b, int N) {
    __shared__ float Wt[DD][DD + 4];   // Wt[k][d] = W[d][k]; pad keeps 16B align + banks
    __shared__ float xs[GR][DD];       // xs[r][k]
    int tid = threadIdx.x;
    for (int i = tid; i < DD * DD; i += 256) {
        int d = i >> 6, k = i & 63;
        Wt[k][d] = W[i];
    }
    int row0 = blockIdx.x * GR;
    int validv = (min(GR, N - row0)) * (DD / 4);   // valid float4 count
    const float4* xv = (const float4*)(x + (size_t)row0 * DD);
#pragma unroll
    for (int i = tid; i < GR * (DD / 4); i += 256) {
        float4 v = (i < validv) ? xv[i] : make_float4(0.f, 0.f, 0.f, 0.f);
        ((float4*)xs)[i] = v;
    }
    __syncthreads();

    int dg = (tid & 15) * 4;     // dim base (0..60)
    int r0 = (tid >> 4) * 4;     // row base within block (0..60)
    float4 bv = *(const float4*)(b + dg);
    float4 a0 = bv, a1 = bv, a2 = bv, a3 = bv;
#pragma unroll
    for (int k = 0; k < DD; k++) {
        float4 wv = *(const float4*)&Wt[k][dg];
        float x0 = xs[r0][k], x1 = xs[r0 + 1][k], x2 = xs[r0 + 2][k], x3 = xs[r0 + 3][k];
        a0.x = fmaf(x0, wv.x, a0.x); a0.y = fmaf(x0, wv.y, a0.y);
        a0.z = fmaf(x0, wv.z, a0.z); a0.w = fmaf(x0, wv.w, a0.w);
        a1.x = fmaf(x1, wv.x, a1.x); a1.y = fmaf(x1, wv.y, a1.y);
        a1.z = fmaf(x1, wv.z, a1.z); a1.w = fmaf(x1, wv.w, a1.w);
        a2.x = fmaf(x2, wv.x, a2.x); a2.y = fmaf(x2, wv.y, a2.y);
        a2.z = fmaf(x2, wv.z, a2.z); a2.w = fmaf(x2, wv.w, a2.w);
        a3.x = fmaf(x3, wv.x, a3.x); a3.y = fmaf(x3, wv.y, a3.y);
        a3.z = fmaf(x3, wv.z, a3.z); a3.w = fmaf(x3, wv.w, a3.w);
    }
    int gr = row0 + r0;
    if (gr + 0 < N) *(float4*)&g_z[(size_t)(gr + 0) * DD + dg] = a0;
    if (gr + 1 < N) *(float4*)&g_z[(size_t)(gr + 1) * DD + dg] = a1;
    if (gr + 2 < N) *(float4*)&g_z[(size_t)(gr + 2) * DD + dg] = a2;
    if (gr + 3 < N) *(float4*)&g_z[(size_t)(gr + 3) * DD + dg] = a3;
}

// ---------------- CSR build ----------------
__global__ void k_zero_deg(int N) {
    int i = blockIdx.x * blockDim.x + threadIdx.x;
    if (i < N) g_deg[i] = 0;
}

__global__ void k_hist(const int* __restrict__ dst, int E) {
    int e = blockIdx.x * blockDim.x + threadIdx.x;
    if (e < E) atomicAdd(&g_deg[dst[e]], 1);
}

__global__ void k_scan1(int N) {
    __shared__ int sm[SCAN_B];
    int t = threadIdx.x;
    int gi = blockIdx.x * SCAN_B + t;
    int v = (gi < N) ? g_deg[gi] : 0;
    sm[t] = v;
    __syncthreads();
#pragma unroll
    for (int o = 1; o < SCAN_B; o <<= 1) {
        int u = (t >= o) ? sm[t - o] : 0;
        __syncthreads();
        sm[t] += u;
        __syncthreads();
    }
    if (gi < N) g_rowstart[gi] = sm[t] - v;
    if (t == SCAN_B - 1) g_bsum[blockIdx.x] = sm[t];
}

__global__ void k_scan2() {
    __shared__ int sm[128];
    int t = threadIdx.x;
    int v = (t < NBLK) ? g_bsum[t] : 0;
    sm[t] = v;
    __syncthreads();
#pragma unroll
    for (int o = 1; o < 128; o <<= 1) {
        int u = (t >= o) ? sm[t - o] : 0;
        __syncthreads();
        sm[t] += u;
        __syncthreads();
    }
    if (t < NBLK) g_bofs[t] = sm[t] - v;
}

__global__ void k_scan3(int N) {
    int i = blockIdx.x * blockDim.x + threadIdx.x;
    if (i < N) {
        g_rowstart[i] += g_bofs[i >> 10];
        g_cursor[i] = 0;
    }
}

__global__ void k_scatter(const int* __restrict__ src, const int* __restrict__ dst, int E) {
    int e = blockIdx.x * blockDim.x + threadIdx.x;
    if (e >= E) return;
    int d = dst[e];
    int pos = g_rowstart[d] + atomicAdd(&g_cursor[d], 1);
    g_csrc[pos] = src[e];
}

// ---------------- Main: HALF-WARP per node; lane-parallel scores ----------------
__global__ void k_main(const float* __restrict__ x, const float* __restrict__ att,
                       float* __restrict__ out, int N) {
    __shared__ float zis[16][DD];   // z_i per half-warp slot
    __shared__ float att_s[DD];
    int tid = threadIdx.x;
    if (tid < DD) att_s[tid] = att[tid];
    __syncthreads();

    int hw = (blockIdx.x * blockDim.x + tid) >> 4;   // half-warp id == node
    int lane16 = tid & 15;
    int sub = (tid >> 4) & 1;
    unsigned mask = 0xFFFFu << (sub * 16);
    int slot = (tid >> 4) & 15;
    if (hw >= N) return;
    int node = hw;

    const float4* Z4 = (const float4*)g_z;
    const float4* X4 = (const float4*)x;

    // load z_i into smem (16 lanes x float4 = full row)
    ((float4*)zis[slot])[lane16] = Z4[(size_t)node * 16 + lane16];
    __syncwarp(mask);

    int start = g_rowstart[node];
    int deg = g_deg[node];

    float m = -INFINITY, s = 0.0f;
    float4 acc = make_float4(0.f, 0.f, 0.f, 0.f);

    for (int base = 0; base < deg; base += 16) {
        bool valid = (base + lane16) < deg;
        int j = valid ? g_csrc[start + base + lane16] : 0;

        // --- score for my edge (lane-local, no shuffles) ---
        float p = -INFINITY;
        if (valid) {
            float acc_p = 0.0f;
            const float4* zj = Z4 + (size_t)j * 16;
#pragma unroll
            for (int l = 0; l < 16; l++) {
                float4 v = zj[l];
                float4 zi = ((const float4*)zis[slot])[l];
                float4 a = ((const float4*)att_s)[l];
                float u0 = v.x + zi.x, u1 = v.y + zi.y, u2 = v.z + zi.z, u3 = v.w + zi.w;
                float r0 = fmaf(0.2f, fminf(u0, 0.f), fmaxf(u0, 0.f));
                float r1 = fmaf(0.2f, fminf(u1, 0.f), fmaxf(u1, 0.f));
                float r2 = fmaf(0.2f, fminf(u2, 0.f), fmaxf(u2, 0.f));
                float r3 = fmaf(0.2f, fminf(u3, 0.f), fmaxf(u3, 0.f));
                acc_p = fmaf(a.x, r0, acc_p);
                acc_p = fmaf(a.y, r1, acc_p);
                acc_p = fmaf(a.z, r2, acc_p);
                acc_p = fmaf(a.w, r3, acc_p);
            }
            p = acc_p;
        }

        // --- chunk softmax (16-wide reductions) ---
        float cm = p;
#pragma unroll
        for (int o = 8; o; o >>= 1) cm = fmaxf(cm, __shfl_xor_sync(mask, cm, o));
        float m_new = fmaxf(m, cm);
        float sc = __expf(m - m_new);          // first chunk: exp(-inf)=0
        float w = valid ? __expf(p - m_new) : 0.0f;
        float ws = w;
#pragma unroll
        for (int o = 8; o; o >>= 1) ws += __shfl_xor_sync(mask, ws, o);
        s = s * sc + ws;
        acc.x *= sc; acc.y *= sc; acc.z *= sc; acc.w *= sc;
        m = m_new;

        // --- accumulate: coalesced x gather, broadcast weights ---
        int cnt = min(16, deg - base);
        for (int k = 0; k < cnt; k++) {
            int jj  = __shfl_sync(mask, j, sub * 16 + k);
            float wk = __shfl_sync(mask, w, sub * 16 + k);
            float4 xv = X4[(size_t)jj * 16 + lane16];
            acc.x = fmaf(wk, xv.x, acc.x);
            acc.y = fmaf(wk, xv.y, acc.y);
            acc.z = fmaf(wk, xv.z, acc.z);
            acc.w = fmaf(wk, xv.w, acc.w);
        }
    }

    float inv = (s > 0.0f) ? (1.0f / s) : 0.0f;
    float4 o4 = make_float4(acc.x * inv, acc.y * inv, acc.z * inv, acc.w * inv);
    ((float4*)out)[(size_t)node * 16 + lane16] = o4;
}

extern "C" void kernel_launch(void* const* d_in, const int* in_sizes, int n_in,
                              void* d_out, int out_size) {
    const float* x   = (const float*)d_in[0];
    const int*   ei  = (const int*)d_in[1];
    const float* W   = (const float*)d_in[2];
    const float* b   = (const float*)d_in[3];
    const float* att = (const float*)d_in[4];
    float* out = (float*)d_out;

    int N = in_sizes[0] / DD;
    int E = in_sizes[1] / 2;
    const int* src = ei;
    const int* dst = ei + E;

    k_gemm<<<(N + GR - 1) / GR, 256>>>(x, W, b, N);

    k_zero_deg<<<(N + 255) / 256, 256>>>(N);
    k_hist<<<(E + 255) / 256, 256>>>(dst, E);
    k_scan1<<<(N + SCAN_B - 1) / SCAN_B, SCAN_B>>>(N);
    k_scan2<<<1, 128>>>();
    k_scan3<<<(N + 255) / 256, 256>>>(N);
    k_scatter<<<(E + 255) / 256, 256>>>(src, dst, E);

    k_main<<<((long long)N * 16 + 255) / 256, 256>>>(x, att, out, N);
}